// round 4
// baseline (speedup 1.0000x reference)
#include <cuda_runtime.h>

// TrueHigherOrderAttention — degenerate-mask reduction.
// The reference mask forces j==i and k==i, so the (j,k) softmax is an exact
// one-hot at (i,i,i):   out = ((x @ Wv1^T) .* (x @ Wv2^T)) @ Wc^T
//
// R4: grid split-K (z=4 -> 512 CTAs, ~14 warps/SM) + packed f32x2 FMA
// (SASS FFMA2; doubles FFMA issue throughput) + B-operand duplicated in smem
// (row-pair accumulators, natural float2 A loads, no pack movs) + two tiny
// float4 reduction kernels merging the K-partials.

constexpr int T    = 256;
constexpr int C    = 512;
constexpr int K    = 512;
constexpr int ZSP  = 4;          // K split factor (grid.z)
constexpr int KZ   = K / ZSP;    // 128 k per CTA
constexpr int KC   = 32;         // k per smem stage
constexpr int NST  = KZ / KC;    // 4 stages

__device__ float g_P [ZSP][T * C];   // stage1 partial (x@Wv1^T)
__device__ float g_Q [ZSP][T * C];   // stage1 partial (x@Wv2^T)
__device__ float g_tmp[T * C];       // (sum P) .* (sum Q)
__device__ float g_O [ZSP][T * C];   // stage2 partial

__device__ __forceinline__ float2 fma2(float2 d, float2 a, float2 b)
{
    unsigned long long dd = *reinterpret_cast<unsigned long long*>(&d);
    unsigned long long aa = *reinterpret_cast<unsigned long long*>(&a);
    unsigned long long bb = *reinterpret_cast<unsigned long long*>(&b);
    asm("fma.rn.f32x2 %0, %1, %2, %0;" : "+l"(dd) : "l"(aa), "l"(bb));
    return *reinterpret_cast<float2*>(&dd);
}

// Partial GEMM over K slice [z*KZ, (z+1)*KZ):
//   P[z] += X @ W1^T   (and Q[z] += X @ W2^T if DUAL) on a 32x32 tile.
// 128 threads; thread microtile = 2 rows x 4 cols held as 4 row-pair float2.
template <bool DUAL>
__global__ __launch_bounds__(128)
void gemm_part_kernel(const float* __restrict__ X,
                      const float* __restrict__ W1,
                      const float* __restrict__ W2,
                      float* __restrict__ Pbuf,
                      float* __restrict__ Qbuf)
{
    __shared__ float xs [KC][32];                // xs[k][row]
    __shared__ float w1d[KC][64];                // w1d[k][2c]={w,w} duplicated
    __shared__ float w2d[DUAL ? KC : 1][64];

    const int i0  = blockIdx.x * 32;
    const int n0  = blockIdx.y * 32;
    const int z   = blockIdx.z;
    const int kb  = z * KZ;
    const int tid = threadIdx.x;
    const int tx  = tid & 7;                     // col group: cols 4tx..4tx+3
    const int ty  = tid >> 3;                    // row group: rows 2ty,2ty+1

    // Loader: lane varies by row -> transposed STS conflict-free-ish.
    const int lr = tid & 31;
    const int lc = tid >> 5;                     // 0..3

    float4 xr[2], w1r[2], w2r[2];
    auto gload = [&](int kc) {
#pragma unroll
        for (int it = 0; it < 2; it++) {
            const int c4 = 4 * lc + 16 * it;     // 0..28
            xr [it] = *(const float4*)&X [(i0 + lr) * C + kb + kc + c4];
            w1r[it] = *(const float4*)&W1[(n0 + lr) * C + kb + kc + c4];
            if (DUAL)
                w2r[it] = *(const float4*)&W2[(n0 + lr) * C + kb + kc + c4];
        }
    };
    gload(0);

    float2 p[4] = {}, q[4] = {};

    for (int st = 0; st < NST; st++) {
        __syncthreads();
#pragma unroll
        for (int it = 0; it < 2; it++) {
            const int c4 = 4 * lc + 16 * it;
            const float xv [4] = {xr [it].x, xr [it].y, xr [it].z, xr [it].w};
            const float w1v[4] = {w1r[it].x, w1r[it].y, w1r[it].z, w1r[it].w};
#pragma unroll
            for (int j = 0; j < 4; j++) {
                xs[c4 + j][lr] = xv[j];
                *(float2*)&w1d[c4 + j][2 * lr] = make_float2(w1v[j], w1v[j]);
            }
            if (DUAL) {
                const float w2v[4] = {w2r[it].x, w2r[it].y, w2r[it].z, w2r[it].w};
#pragma unroll
                for (int j = 0; j < 4; j++)
                    *(float2*)&w2d[c4 + j][2 * lr] = make_float2(w2v[j], w2v[j]);
            }
        }
        __syncthreads();

        if (st + 1 < NST) gload((st + 1) * KC);  // prefetch under compute

#pragma unroll
        for (int k = 0; k < KC; k++) {
            const float2 a2 = *(const float2*)&xs[k][2 * ty];   // {row0,row1}
            const float4 bA = *(const float4*)&w1d[k][8 * tx];      // {b0,b0,b1,b1}
            const float4 bB = *(const float4*)&w1d[k][8 * tx + 4];  // {b2,b2,b3,b3}
            p[0] = fma2(p[0], a2, make_float2(bA.x, bA.y));
            p[1] = fma2(p[1], a2, make_float2(bA.z, bA.w));
            p[2] = fma2(p[2], a2, make_float2(bB.x, bB.y));
            p[3] = fma2(p[3], a2, make_float2(bB.z, bB.w));
            if (DUAL) {
                const float4 cA = *(const float4*)&w2d[k][8 * tx];
                const float4 cB = *(const float4*)&w2d[k][8 * tx + 4];
                q[0] = fma2(q[0], a2, make_float2(cA.x, cA.y));
                q[1] = fma2(q[1], a2, make_float2(cA.z, cA.w));
                q[2] = fma2(q[2], a2, make_float2(cB.x, cB.y));
                q[3] = fma2(q[3], a2, make_float2(cB.z, cB.w));
            }
        }
    }

    // Store partials: p[c] = {row 2ty, row 2ty+1} at col 4tx+c.
    const long base = (long)z * (T * C);
    const int  r0   = i0 + 2 * ty;
    float4 v0 = make_float4(p[0].x, p[1].x, p[2].x, p[3].x);
    float4 v1 = make_float4(p[0].y, p[1].y, p[2].y, p[3].y);
    *(float4*)&Pbuf[base + (long)(r0    ) * C + n0 + 4 * tx] = v0;
    *(float4*)&Pbuf[base + (long)(r0 + 1) * C + n0 + 4 * tx] = v1;
    if (DUAL) {
        float4 u0 = make_float4(q[0].x, q[1].x, q[2].x, q[3].x);
        float4 u1 = make_float4(q[0].y, q[1].y, q[2].y, q[3].y);
        *(float4*)&Qbuf[base + (long)(r0    ) * C + n0 + 4 * tx] = u0;
        *(float4*)&Qbuf[base + (long)(r0 + 1) * C + n0 + 4 * tx] = u1;
    }
}

// tmp = (sum_z P) .* (sum_z Q)
__global__ __launch_bounds__(256)
void reduce_prod_kernel(const float* __restrict__ P,
                        const float* __restrict__ Q,
                        float* __restrict__ OUT)
{
    const int i = blockIdx.x * blockDim.x + threadIdx.x;   // float4 index
    float4 sp = *(const float4*)&P[4 * i];
    float4 sq = *(const float4*)&Q[4 * i];
#pragma unroll
    for (int zz = 1; zz < ZSP; zz++) {
        const float4 a = *(const float4*)&P[zz * (T * C) + 4 * i];
        const float4 b = *(const float4*)&Q[zz * (T * C) + 4 * i];
        sp.x += a.x; sp.y += a.y; sp.z += a.z; sp.w += a.w;
        sq.x += b.x; sq.y += b.y; sq.z += b.z; sq.w += b.w;
    }
    float4 r = make_float4(sp.x * sq.x, sp.y * sq.y, sp.z * sq.z, sp.w * sq.w);
    *(float4*)&OUT[4 * i] = r;
}

// out = sum_z O
__global__ __launch_bounds__(256)
void reduce_sum_kernel(const float* __restrict__ O,
                       float* __restrict__ OUT)
{
    const int i = blockIdx.x * blockDim.x + threadIdx.x;
    float4 s = *(const float4*)&O[4 * i];
#pragma unroll
    for (int zz = 1; zz < ZSP; zz++) {
        const float4 a = *(const float4*)&O[zz * (T * C) + 4 * i];
        s.x += a.x; s.y += a.y; s.z += a.z; s.w += a.w;
    }
    *(float4*)&OUT[4 * i] = s;
}

extern "C" void kernel_launch(void* const* d_in, const int* in_sizes, int n_in,
                              void* d_out, int out_size)
{
    // metadata order: x, Wq, Wk1, Wk2, Wv1, Wv2, Wc
    const float* x   = (const float*)d_in[0];
    const float* Wv1 = (const float*)d_in[4];
    const float* Wv2 = (const float*)d_in[5];
    const float* Wc  = (const float*)d_in[6];
    float* out = (float*)d_out;

    float *P, *Q, *tmp, *O;
    cudaGetSymbolAddress((void**)&P,   g_P);
    cudaGetSymbolAddress((void**)&Q,   g_Q);
    cudaGetSymbolAddress((void**)&tmp, g_tmp);
    cudaGetSymbolAddress((void**)&O,   g_O);

    dim3 gpart(T / 32, C / 32, ZSP);            // 8 x 16 x 4 = 512 CTAs
    const int nred = (T * C / 4) / 256;         // 128 CTAs

    gemm_part_kernel<true ><<<gpart, 128>>>(x, Wv1, Wv2, P, Q);
    reduce_prod_kernel<<<nred, 256>>>(P, Q, tmp);
    gemm_part_kernel<false><<<gpart, 128>>>(tmp, Wc, nullptr, O, nullptr);
    reduce_sum_kernel<<<nred, 256>>>(O, out);
}